// round 9
// baseline (speedup 1.0000x reference)
#include <cuda_runtime.h>
#include <math.h>
#include <stdint.h>

#define BB 4
#define DM 512
#define DFF 2048
#define NH 8
#define HD 64
#define CDIV(a,b) (((a)+(b)-1)/(b))

__device__ float g_x  [BB*2048*DM];
__device__ float g_tmp[BB*2048*DM];
__device__ float g_q  [BB*2048*DM];
__device__ float g_k  [BB*2048*DM];
__device__ float g_v  [BB*2048*DM];
__device__ float g_ctx[BB*2048*DM];
__device__ float g_ffn[BB*2048*DFF];
__device__ float g_M  [BB*NH*2048];
__device__ float g_upd[BB*NH*64*HD];
__device__ float g_vm [BB*NH*HD];
__device__ float g_stats[2*DM];
__device__ int   g_top[BB*NH*64];
__device__ int   g_idx[2048*64];

__host__ __device__ inline void tf2x32(unsigned k0, unsigned k1,
                                       unsigned x0, unsigned x1,
                                       unsigned &o0, unsigned &o1) {
  unsigned ks2 = k0 ^ k1 ^ 0x1BD11BDAu;
#define TFR(r) x0 += x1; x1 = ((x1<<(r))|(x1>>(32-(r)))); x1 ^= x0;
  x0 += k0; x1 += k1;
  TFR(13) TFR(15) TFR(26) TFR(6)
  x0 += k1;  x1 += ks2 + 1u;
  TFR(17) TFR(29) TFR(16) TFR(24)
  x0 += ks2; x1 += k0 + 2u;
  TFR(13) TFR(15) TFR(26) TFR(6)
  x0 += k0;  x1 += k1 + 3u;
  TFR(17) TFR(29) TFR(16) TFR(24)
  x0 += k1;  x1 += ks2 + 4u;
  TFR(13) TFR(15) TFR(26) TFR(6)
  x0 += ks2; x1 += k0 + 5u;
#undef TFR
  o0 = x0; o1 = x1;
}

// Partitionable random_bits on the randint-internal subkey k2:
// element at flat index j = (o0^o1) of threefry(k2, (0, j)); idx = bits & (L-1).
__global__ void rng_idx_kernel(unsigned k0, unsigned k1, int Lc, int n, int* idx) {
  int j = blockIdx.x * blockDim.x + threadIdx.x;
  if (j >= n) return;
  unsigned o0, o1;
  tf2x32(k0, k1, 0u, (unsigned)j, o0, o1);
  idx[j] = (int)((o0 ^ o1) & (unsigned)(Lc - 1));
}

__global__ void tok_conv_pe(const float* __restrict__ xe, const float* __restrict__ w,
                            float* __restrict__ X) {
  __shared__ float sx[3][32];
  int bl = blockIdx.x;
  int b = bl >> 11, l = bl & 2047;
  int t = threadIdx.x;
  if (t < 96) {
    int kk = t / 32, i = t % 32;
    int l2 = (l + kk - 1 + 2048) & 2047;
    sx[kk][i] = xe[((size_t)(b*2048 + l2))*32 + i];
  }
  __syncthreads();
  const float* wr = w + (size_t)t * 96;
  float s = 0.f;
#pragma unroll
  for (int i = 0; i < 32; i++)
    s += sx[0][i]*wr[i*3] + sx[1][i]*wr[i*3+1] + sx[2][i]*wr[i*3+2];
  int j = t >> 1;
  float xf = (float)(2*j) * (float)(-(9.210340371976184/512.0));
  float divf = (float)exp((double)xf);
  float angf = (float)l * divf;
  double sv = (t & 1) ? cos((double)angf) : sin((double)angf);
  X[((size_t)bl)*DM + t] = s + (float)sv;
}

__global__ void gemm_kernel(const float* __restrict__ A, const float* __restrict__ B,
                            int ldb, int bstride,
                            const float* __restrict__ bias, const float* __restrict__ res,
                            float* __restrict__ C,
                            int M, int N, int K, int Lc, int shift, int gelu, int accum) {
  __shared__ float As[16][64];
  __shared__ float Bs[16][64];
  int tid = threadIdx.x;
  int bm = blockIdx.y * 64, bn = blockIdx.x * 64;
  int rloc = tid >> 2;
  int kq   = (tid & 3) * 4;

  int row = bm + rloc;
  long arow = -1;
  if (row < M) {
    int b = row / Lc, l = row % Lc;
    int l2 = l + shift;
    if (l2 < 0) l2 += Lc; else if (l2 >= Lc) l2 -= Lc;
    arow = (long)b * Lc + l2;
  }
  int colB = bn + rloc;
  bool bok = (colB < N);
  const float* Brow = B + (size_t)(bok ? colB : 0) * (size_t)ldb;

  int tm = tid & 15, tn = tid >> 4;
  float acc[4][4];
#pragma unroll
  for (int i = 0; i < 4; i++)
#pragma unroll
    for (int j = 0; j < 4; j++) acc[i][j] = 0.f;

  for (int k0 = 0; k0 < K; k0 += 16) {
    float4 a4 = make_float4(0.f,0.f,0.f,0.f);
    if (arow >= 0) a4 = *(const float4*)&A[(size_t)arow * K + k0 + kq];
    As[kq+0][rloc] = a4.x; As[kq+1][rloc] = a4.y;
    As[kq+2][rloc] = a4.z; As[kq+3][rloc] = a4.w;
#pragma unroll
    for (int j = 0; j < 4; j++) {
      float bv = bok ? Brow[(size_t)(k0 + kq + j) * bstride] : 0.f;
      Bs[kq+j][rloc] = bv;
    }
    __syncthreads();
#pragma unroll
    for (int kk = 0; kk < 16; kk++) {
      float4 av4 = *(const float4*)&As[kk][tm*4];
      float4 bv4 = *(const float4*)&Bs[kk][tn*4];
      float av[4] = {av4.x, av4.y, av4.z, av4.w};
      float bv[4] = {bv4.x, bv4.y, bv4.z, bv4.w};
#pragma unroll
      for (int i = 0; i < 4; i++)
#pragma unroll
        for (int j = 0; j < 4; j++) acc[i][j] += av[i]*bv[j];
    }
    __syncthreads();
  }

  int rbase = bm + tm*4, cbase = bn + tn*4;
#pragma unroll
  for (int i = 0; i < 4; i++) {
    int r = rbase + i;
    if (r >= M) continue;
#pragma unroll
    for (int j = 0; j < 4; j++) {
      int c = cbase + j;
      if (c >= N) continue;
      float vv = acc[i][j];
      size_t oi = (size_t)r * N + c;
      if (accum) { C[oi] += vv; }
      else {
        if (bias) vv += bias[c];
        if (gelu) vv = 0.5f * vv * (1.f + erff(vv * 0.70710678118654752f));
        if (res)  vv += res[oi];
        C[oi] = vv;
      }
    }
  }
}

__global__ void sample_m_kernel(const float* __restrict__ Q, const float* __restrict__ K,
                                const int* __restrict__ idx, float* __restrict__ Mout,
                                int Lc, int sk) {
  int gw = (blockIdx.x * blockDim.x + threadIdx.x) >> 5;
  int lane = threadIdx.x & 31;
  if (gw >= BB*NH*Lc) return;
  int l = gw % Lc, h = (gw / Lc) & 7, b = gw / (Lc * NH);
  const float* qr = Q + ((size_t)(b*Lc + l))*DM + h*HD;
  float2 q2 = *(const float2*)(qr + lane*2);
  const int* rw = idx + (size_t)l * sk;
  float mx = -3.0e38f, sm = 0.f;
  for (int u = 0; u < sk; u++) {
    const float* kr = K + ((size_t)(b*Lc + rw[u]))*DM + h*HD;
    float2 k2 = *(const float2*)(kr + lane*2);
    float p = q2.x*k2.x + q2.y*k2.y;
#pragma unroll
    for (int o = 16; o; o >>= 1) p += __shfl_xor_sync(0xffffffffu, p, o);
    mx = fmaxf(mx, p); sm += p;
  }
  if (!lane) Mout[gw] = mx - sm / (float)Lc;
}

__global__ void topk_kernel(float* __restrict__ M, int* __restrict__ top, int Lc, int ntop) {
  float* row = M + (size_t)blockIdx.x * Lc;
  __shared__ float sv[256];
  __shared__ int   si[256];
  int t = threadIdx.x;
  for (int it = 0; it < ntop; it++) {
    float bv = -3.0e38f; int bi = 0x7fffffff;
    for (int i = t; i < Lc; i += 256) {
      float vv = row[i];
      if (vv > bv) { bv = vv; bi = i; }
    }
    sv[t] = bv; si[t] = bi; __syncthreads();
    for (int s = 128; s; s >>= 1) {
      if (t < s && (sv[t+s] > sv[t] || (sv[t+s] == sv[t] && si[t+s] < si[t]))) {
        sv[t] = sv[t+s]; si[t] = si[t+s];
      }
      __syncthreads();
    }
    if (!t) { top[blockIdx.x * ntop + it] = si[0]; row[si[0]] = -3.0e38f; }
    __syncthreads();
  }
}

__global__ void vmean_kernel(const float* __restrict__ V, float* __restrict__ vm, int Lc) {
  int bh = blockIdx.x, b = bh >> 3, h = bh & 7;
  int t = threadIdx.x, d = t & 63, sl = t >> 6;
  float s = 0.f;
  for (int l = sl; l < Lc; l += 4) s += V[((size_t)(b*Lc + l))*DM + h*HD + d];
  __shared__ float sp[256];
  sp[t] = s; __syncthreads();
  if (t < 64) vm[bh*HD + t] = (sp[t] + sp[t+64] + sp[t+128] + sp[t+192]) / (float)Lc;
}

__global__ void attn_kernel(const float* __restrict__ Q, const float* __restrict__ K,
                            const float* __restrict__ V, const int* __restrict__ top,
                            float* __restrict__ upd, int Lc, int ntop) {
  int u = blockIdx.x % ntop, bh = blockIdx.x / ntop;
  int b = bh >> 3, h = bh & 7;
  int t = threadIdx.x, lane = t & 31, w = t >> 5;
  __shared__ float sc[2048];
  __shared__ float qrow[64];
  __shared__ float sr[256];
  int ql = top[bh*ntop + u];
  if (t < 64) qrow[t] = Q[((size_t)(b*Lc + ql))*DM + h*HD + t];
  __syncthreads();
  float qa = qrow[lane*2], qb = qrow[lane*2+1];
  for (int kk = w; kk < Lc; kk += 8) {
    const float* kr = K + ((size_t)(b*Lc + kk))*DM + h*HD;
    float p = qa*kr[lane*2] + qb*kr[lane*2+1];
#pragma unroll
    for (int o = 16; o; o >>= 1) p += __shfl_xor_sync(0xffffffffu, p, o);
    if (!lane) sc[kk] = p * 0.125f;
  }
  __syncthreads();
  float mx = -3.0e38f;
  for (int i = t; i < Lc; i += 256) mx = fmaxf(mx, sc[i]);
  sr[t] = mx; __syncthreads();
  for (int s = 128; s; s >>= 1) { if (t < s) sr[t] = fmaxf(sr[t], sr[t+s]); __syncthreads(); }
  mx = sr[0]; __syncthreads();
  float sum = 0.f;
  for (int i = t; i < Lc; i += 256) { float e = expf(sc[i] - mx); sc[i] = e; sum += e; }
  sr[t] = sum; __syncthreads();
  for (int s = 128; s; s >>= 1) { if (t < s) sr[t] += sr[t+s]; __syncthreads(); }
  float inv = 1.f / sr[0];
  __syncthreads();
  int d = t & 63, sl = t >> 6;
  float a = 0.f;
  for (int kk = sl; kk < Lc; kk += 4)
    a += (sc[kk] * inv) * V[((size_t)(b*Lc + kk))*DM + h*HD + d];
  sr[t] = a; __syncthreads();
  if (t < 64)
    upd[((size_t)bh*ntop + u)*HD + t] = sr[t] + sr[t+64] + sr[t+128] + sr[t+192];
}

__global__ void ctx_fill(const float* __restrict__ vm, float* __restrict__ ctx, int Lc) {
  size_t i = (size_t)blockIdx.x * blockDim.x + threadIdx.x;
  if (i >= (size_t)BB * Lc * DM) return;
  int c = (int)(i & 511);
  int b = (int)((i >> 9) / (size_t)Lc);
  ctx[i] = vm[(b*NH + (c >> 6))*HD + (c & 63)];
}

__global__ void ctx_scatter(const float* __restrict__ upd, const int* __restrict__ top,
                            float* __restrict__ ctx, int Lc, int ntop) {
  int u = blockIdx.x % ntop, bh = blockIdx.x / ntop;
  int b = bh >> 3, h = bh & 7;
  int l = top[bh*ntop + u];
  ctx[((size_t)(b*Lc + l))*DM + h*HD + threadIdx.x] =
      upd[((size_t)bh*ntop + u)*HD + threadIdx.x];
}

__global__ void ln_kernel(const float* __restrict__ X, const float* __restrict__ g,
                          const float* __restrict__ be, float* __restrict__ Y) {
  int r = blockIdx.x, t = threadIdx.x;
  const float* x = X + (size_t)r * DM;
  float* y = Y + (size_t)r * DM;
  float v0 = x[t], v1 = x[t+128], v2 = x[t+256], v3 = x[t+384];
  __shared__ float sr[128];
  sr[t] = v0+v1+v2+v3; __syncthreads();
  for (int s = 64; s; s >>= 1) { if (t < s) sr[t] += sr[t+s]; __syncthreads(); }
  float mu = sr[0] * (1.f/512.f); __syncthreads();
  float d0 = v0-mu, d1 = v1-mu, d2 = v2-mu, d3 = v3-mu;
  sr[t] = d0*d0 + d1*d1 + d2*d2 + d3*d3; __syncthreads();
  for (int s = 64; s; s >>= 1) { if (t < s) sr[t] += sr[t+s]; __syncthreads(); }
  float rstd = rsqrtf(sr[0] * (1.f/512.f) + 1e-5f);
  y[t]     = d0*rstd*g[t]     + be[t];
  y[t+128] = d1*rstd*g[t+128] + be[t+128];
  y[t+256] = d2*rstd*g[t+256] + be[t+256];
  y[t+384] = d3*rstd*g[t+384] + be[t+384];
}

__global__ void bn_stats(const float* __restrict__ Y, int M, float* __restrict__ stats) {
  int c = blockIdx.x, t = threadIdx.x;
  double s = 0.0, s2 = 0.0;
  for (int r = t; r < M; r += 256) {
    float vv = Y[(size_t)r*DM + c];
    s += vv; s2 += (double)vv*vv;
  }
  __shared__ double sh[256], sh2[256];
  sh[t] = s; sh2[t] = s2; __syncthreads();
  for (int st = 128; st; st >>= 1) {
    if (t < st) { sh[t] += sh[t+st]; sh2[t] += sh2[t+st]; }
    __syncthreads();
  }
  if (!t) {
    double mu = sh[0] / M;
    stats[c] = (float)mu;
    stats[DM + c] = (float)(sh2[0] / M - mu*mu);
  }
}

__global__ void bn_elu(float* __restrict__ Y, const float* __restrict__ stats,
                       const float* __restrict__ g, const float* __restrict__ b, int M) {
  size_t i = (size_t)blockIdx.x * blockDim.x + threadIdx.x;
  if (i >= (size_t)M * DM) return;
  int c = (int)(i & 511);
  float vv = (Y[i] - stats[c]) * rsqrtf(stats[DM+c] + 1e-5f) * g[c] + b[c];
  Y[i] = vv > 0.f ? vv : expm1f(vv);
}

__global__ void maxpool_kernel(const float* __restrict__ Y, float* __restrict__ X, int Lout) {
  size_t i = (size_t)blockIdx.x * blockDim.x + threadIdx.x;
  if (i >= (size_t)BB * Lout * DM) return;
  int c = (int)(i & 511);
  size_t bt = i >> 9;
  int b = (int)(bt / (size_t)Lout), t = (int)(bt % (size_t)Lout);
  int L = Lout * 2;
  float m = Y[((size_t)(b*L + 2*t))*DM + c];
  m = fmaxf(m, Y[((size_t)(b*L + 2*t + 1))*DM + c]);
  if (t > 0) m = fmaxf(m, Y[((size_t)(b*L + 2*t - 1))*DM + c]);
  X[i] = m;
}

extern "C" void kernel_launch(void* const* d_in, const int* in_sizes, int n_in,
                              void* d_out, int out_size) {
  const float* x_enc  = (const float*)d_in[0];
  const float* tok_w  = (const float*)d_in[1];
  const float* Wq     = (const float*)d_in[2];
  const float* bq     = (const float*)d_in[3];
  const float* Wk     = (const float*)d_in[4];
  const float* bk     = (const float*)d_in[5];
  const float* Wv     = (const float*)d_in[6];
  const float* bv     = (const float*)d_in[7];
  const float* Wo     = (const float*)d_in[8];
  const float* bo     = (const float*)d_in[9];
  const float* W1     = (const float*)d_in[10];
  const float* b1     = (const float*)d_in[11];
  const float* W2     = (const float*)d_in[12];
  const float* b2     = (const float*)d_in[13];
  const float* ln1_g  = (const float*)d_in[14];
  const float* ln1_b  = (const float*)d_in[15];
  const float* ln2_g  = (const float*)d_in[16];
  const float* ln2_b  = (const float*)d_in[17];
  const float* conv_w = (const float*)d_in[18];
  const float* conv_b = (const float*)d_in[19];
  const float* bn_g   = (const float*)d_in[20];
  const float* bn_b   = (const float*)d_in[21];
  const float* normf_g= (const float*)d_in[22];
  const float* normf_b= (const float*)d_in[23];
  const float* proj_w = (const float*)d_in[24];
  const float* proj_b = (const float*)d_in[25];
  float* out = (float*)d_out;

  float *x,*tmp,*q,*k,*v,*ctx,*ffn,*Mb,*upd,*vm,*stats;
  int *top,*idx;
  cudaGetSymbolAddress((void**)&x,   g_x);
  cudaGetSymbolAddress((void**)&tmp, g_tmp);
  cudaGetSymbolAddress((void**)&q,   g_q);
  cudaGetSymbolAddress((void**)&k,   g_k);
  cudaGetSymbolAddress((void**)&v,   g_v);
  cudaGetSymbolAddress((void**)&ctx, g_ctx);
  cudaGetSymbolAddress((void**)&ffn, g_ffn);
  cudaGetSymbolAddress((void**)&Mb,  g_M);
  cudaGetSymbolAddress((void**)&upd, g_upd);
  cudaGetSymbolAddress((void**)&vm,  g_vm);
  cudaGetSymbolAddress((void**)&stats, g_stats);
  cudaGetSymbolAddress((void**)&top, g_top);
  cudaGetSymbolAddress((void**)&idx, g_idx);

  // Partitionable (foldlike) split: keys[i] = threefry((0,42), (0,i)).
  // randint internal: k1,k2 = split(keys[i]) -> k2 = threefry(keys[i], (0,1)).
  unsigned K0s[2], K1s[2], R0s[2], R1s[2];
  tf2x32(0u, 42u, 0u, 0u, K0s[0], K1s[0]);
  tf2x32(0u, 42u, 0u, 1u, K0s[1], K1s[1]);
  tf2x32(K0s[0], K1s[0], 0u, 1u, R0s[0], R1s[0]);
  tf2x32(K0s[1], K1s[1], 0u, 1u, R0s[1], R1s[1]);

  tok_conv_pe<<<BB*2048, 512>>>(x_enc, tok_w, x);

  int Lc = 2048;
  for (int i = 0; i < 2; i++) {
    int M = BB * Lc;
    int ntop = (i == 0) ? 40 : 35;
    int sk = ntop;
    dim3 thr(256);
    dim3 g512(512/64, M/64);
    size_t WO = (size_t)i*512*512, BO = (size_t)i*512;

    gemm_kernel<<<g512,thr>>>(x, Wq+WO, 512,1, bq+BO, nullptr, q, M,512,512, Lc,0,0,0);
    gemm_kernel<<<g512,thr>>>(x, Wk+WO, 512,1, bk+BO, nullptr, k, M,512,512, Lc,0,0,0);
    gemm_kernel<<<g512,thr>>>(x, Wv+WO, 512,1, bv+BO, nullptr, v, M,512,512, Lc,0,0,0);

    int n = Lc * sk;
    rng_idx_kernel<<<CDIV(n,256),256>>>(R0s[i], R1s[i], Lc, n, idx);

    sample_m_kernel<<<CDIV(BB*NH*Lc*32,256),256>>>(q, k, idx, Mb, Lc, sk);
    topk_kernel<<<BB*NH,256>>>(Mb, top, Lc, ntop);
    vmean_kernel<<<BB*NH,256>>>(v, vm, Lc);
    ctx_fill<<<CDIV((size_t)M*512,256),256>>>(vm, ctx, Lc);
    attn_kernel<<<BB*NH*ntop,256>>>(q, k, v, top, upd, Lc, ntop);
    ctx_scatter<<<BB*NH*ntop,64>>>(upd, top, ctx, Lc, ntop);

    gemm_kernel<<<g512,thr>>>(ctx, Wo+WO, 512,1, bo+BO, x, tmp, M,512,512, Lc,0,0,0);
    ln_kernel<<<M,128>>>(tmp, ln1_g+BO, ln1_b+BO, x);

    dim3 gff(DFF/64, M/64);
    gemm_kernel<<<gff,thr>>>(x, W1+(size_t)i*DFF*512, 512,1, b1+(size_t)i*DFF, nullptr,
                             ffn, M,DFF,512, Lc,0,1,0);
    gemm_kernel<<<g512,thr>>>(ffn, W2+(size_t)i*512*DFF, DFF,1, b2+BO, x, tmp,
                              M,512,DFF, Lc,0,0,0);
    ln_kernel<<<M,128>>>(tmp, ln2_g+BO, ln2_b+BO, x);

    if (i == 0) {
      for (int kk = 0; kk < 3; kk++) {
        gemm_kernel<<<g512,thr>>>(x, conv_w + kk, 512*3, 3,
                                  kk==0 ? conv_b : nullptr, nullptr, tmp,
                                  M,512,512, Lc, kk-1, 0, kk>0 ? 1 : 0);
      }
      bn_stats<<<512,256>>>(tmp, M, stats);
      bn_elu<<<CDIV((size_t)M*512,256),256>>>(tmp, stats, bn_g, bn_b, M);
      maxpool_kernel<<<CDIV((size_t)(M/2)*512,256),256>>>(tmp, x, Lc/2);
      Lc = 1024;
    }
  }

  int M = BB * Lc;
  ln_kernel<<<M,128>>>(x, normf_g, normf_b, tmp);
  dim3 gproj(1, M/64);
  gemm_kernel<<<gproj,dim3(256)>>>(tmp, proj_w, 512,1, proj_b, nullptr, out,
                                   M,32,512, Lc,0,0,0);
}

// round 10
// speedup vs baseline: 1.2460x; 1.2460x over previous
#include <cuda_runtime.h>
#include <math.h>
#include <stdint.h>

#define BB 4
#define DM 512
#define DFF 2048
#define NH 8
#define HD 64
#define CDIV(a,b) (((a)+(b)-1)/(b))

__device__ float g_x  [BB*2048*DM];
__device__ float g_tmp[BB*2048*DM];
__device__ float g_q  [BB*2048*DM];
__device__ float g_k  [BB*2048*DM];
__device__ float g_v  [BB*2048*DM];
__device__ float g_ctx[BB*2048*DM];
__device__ float g_ffn[BB*2048*DFF];
__device__ float g_M  [BB*NH*2048];
__device__ float g_upd[BB*NH*64*HD];
__device__ float g_vm [BB*NH*HD];
__device__ float g_stats[2*DM];
__device__ int   g_top[BB*NH*64];
__device__ int   g_idx[2048*64];

__host__ __device__ inline void tf2x32(unsigned k0, unsigned k1,
                                       unsigned x0, unsigned x1,
                                       unsigned &o0, unsigned &o1) {
  unsigned ks2 = k0 ^ k1 ^ 0x1BD11BDAu;
#define TFR(r) x0 += x1; x1 = ((x1<<(r))|(x1>>(32-(r)))); x1 ^= x0;
  x0 += k0; x1 += k1;
  TFR(13) TFR(15) TFR(26) TFR(6)
  x0 += k1;  x1 += ks2 + 1u;
  TFR(17) TFR(29) TFR(16) TFR(24)
  x0 += ks2; x1 += k0 + 2u;
  TFR(13) TFR(15) TFR(26) TFR(6)
  x0 += k0;  x1 += k1 + 3u;
  TFR(17) TFR(29) TFR(16) TFR(24)
  x0 += k1;  x1 += ks2 + 4u;
  TFR(13) TFR(15) TFR(26) TFR(6)
  x0 += ks2; x1 += k0 + 5u;
#undef TFR
  o0 = x0; o1 = x1;
}

__global__ void rng_idx_kernel(unsigned k0, unsigned k1, int Lc, int n, int* idx) {
  int j = blockIdx.x * blockDim.x + threadIdx.x;
  if (j >= n) return;
  unsigned o0, o1;
  tf2x32(k0, k1, 0u, (unsigned)j, o0, o1);
  idx[j] = (int)((o0 ^ o1) & (unsigned)(Lc - 1));
}

__global__ void tok_conv_pe(const float* __restrict__ xe, const float* __restrict__ w,
                            float* __restrict__ X) {
  __shared__ float sx[3][32];
  int bl = blockIdx.x;
  int b = bl >> 11, l = bl & 2047;
  int t = threadIdx.x;
  if (t < 96) {
    int kk = t / 32, i = t % 32;
    int l2 = (l + kk - 1 + 2048) & 2047;
    sx[kk][i] = xe[((size_t)(b*2048 + l2))*32 + i];
  }
  __syncthreads();
  const float* wr = w + (size_t)t * 96;
  float s = 0.f;
#pragma unroll
  for (int i = 0; i < 32; i++)
    s += sx[0][i]*wr[i*3] + sx[1][i]*wr[i*3+1] + sx[2][i]*wr[i*3+2];
  int j = t >> 1;
  float xf = (float)(2*j) * (float)(-(9.210340371976184/512.0));
  float divf = (float)exp((double)xf);
  float angf = (float)l * divf;
  double sv = (t & 1) ? cos((double)angf) : sin((double)angf);
  X[((size_t)bl)*DM + t] = s + (float)sv;
}

// 128x128x16 tile SGEMM, 256 thr, 8x8 microtile (4+4 split), reg-prefetch.
// C[M,N] = Ashift[M,K] @ B^T (+bias)(+gelu)(+res); B(n,k) at B[n*ldb+k*bstride].
__global__ void __launch_bounds__(256, 2)
gemm_kernel(const float* __restrict__ A, const float* __restrict__ B,
            int ldb, int bstride,
            const float* __restrict__ bias, const float* __restrict__ res,
            float* __restrict__ C,
            int M, int N, int K, int Lc, int shift, int gelu, int accum) {
  __shared__ float As[16][128];
  __shared__ float Bs[16][128];
  int tid = threadIdx.x;
  int bm = blockIdx.y * 128, bn = blockIdx.x * 128;
  int lrow = tid >> 1;            // 0..127
  int lcol = (tid & 1) * 8;       // 0 or 8

  int row = bm + lrow;
  long arow;
  {
    int rr = (row < M) ? row : (M - 1);
    int b = rr / Lc, l = rr % Lc;
    int l2 = l + shift;
    if (l2 < 0) l2 += Lc; else if (l2 >= Lc) l2 -= Lc;
    arow = (long)b * Lc + l2;
  }
  const float* Arow = A + (size_t)arow * K;
  int colB = bn + lrow;
  bool bok = (colB < N);
  const float* Brow = B + (size_t)(bok ? colB : 0) * (size_t)ldb;

  int tm = tid & 15, tn = tid >> 4;
  float acc[8][8];
#pragma unroll
  for (int i = 0; i < 8; i++)
#pragma unroll
    for (int j = 0; j < 8; j++) acc[i][j] = 0.f;

  float ra[8], rb[8];
  // prefetch k-tile 0
  {
    float4 a0 = *(const float4*)(Arow + lcol);
    float4 a1 = *(const float4*)(Arow + lcol + 4);
    ra[0]=a0.x; ra[1]=a0.y; ra[2]=a0.z; ra[3]=a0.w;
    ra[4]=a1.x; ra[5]=a1.y; ra[6]=a1.z; ra[7]=a1.w;
    if (bstride == 1) {
      float4 b0 = bok ? *(const float4*)(Brow + lcol) : make_float4(0,0,0,0);
      float4 b1 = bok ? *(const float4*)(Brow + lcol + 4) : make_float4(0,0,0,0);
      rb[0]=b0.x; rb[1]=b0.y; rb[2]=b0.z; rb[3]=b0.w;
      rb[4]=b1.x; rb[5]=b1.y; rb[6]=b1.z; rb[7]=b1.w;
    } else {
#pragma unroll
      for (int j = 0; j < 8; j++)
        rb[j] = bok ? Brow[(size_t)(lcol + j) * bstride] : 0.f;
    }
  }

  int nk = K >> 4;
  for (int kt = 0; kt < nk; kt++) {
#pragma unroll
    for (int j = 0; j < 8; j++) { As[lcol+j][lrow] = ra[j]; Bs[lcol+j][lrow] = rb[j]; }
    __syncthreads();
    if (kt + 1 < nk) {
      int k0 = (kt + 1) << 4;
      float4 a0 = *(const float4*)(Arow + k0 + lcol);
      float4 a1 = *(const float4*)(Arow + k0 + lcol + 4);
      ra[0]=a0.x; ra[1]=a0.y; ra[2]=a0.z; ra[3]=a0.w;
      ra[4]=a1.x; ra[5]=a1.y; ra[6]=a1.z; ra[7]=a1.w;
      if (bstride == 1) {
        float4 b0 = bok ? *(const float4*)(Brow + k0 + lcol) : make_float4(0,0,0,0);
        float4 b1 = bok ? *(const float4*)(Brow + k0 + lcol + 4) : make_float4(0,0,0,0);
        rb[0]=b0.x; rb[1]=b0.y; rb[2]=b0.z; rb[3]=b0.w;
        rb[4]=b1.x; rb[5]=b1.y; rb[6]=b1.z; rb[7]=b1.w;
      } else {
#pragma unroll
        for (int j = 0; j < 8; j++)
          rb[j] = bok ? Brow[(size_t)(k0 + lcol + j) * bstride] : 0.f;
      }
    }
#pragma unroll
    for (int kk = 0; kk < 16; kk++) {
      float af[8], bf[8];
      *(float4*)(af)   = *(const float4*)&As[kk][tm*4];
      *(float4*)(af+4) = *(const float4*)&As[kk][64 + tm*4];
      *(float4*)(bf)   = *(const float4*)&Bs[kk][tn*4];
      *(float4*)(bf+4) = *(const float4*)&Bs[kk][64 + tn*4];
#pragma unroll
      for (int i = 0; i < 8; i++)
#pragma unroll
        for (int j = 0; j < 8; j++) acc[i][j] += af[i]*bf[j];
    }
    __syncthreads();
  }

#pragma unroll
  for (int i = 0; i < 8; i++) {
    int r = bm + (i >> 2)*64 + tm*4 + (i & 3);
    if (r >= M) continue;
#pragma unroll
    for (int j = 0; j < 8; j++) {
      int c = bn + (j >> 2)*64 + tn*4 + (j & 3);
      if (c >= N) continue;
      float vv = acc[i][j];
      size_t oi = (size_t)r * N + c;
      if (accum) { C[oi] += vv; }
      else {
        if (bias) vv += bias[c];
        if (gelu) vv = 0.5f * vv * (1.f + erff(vv * 0.70710678118654752f));
        if (res)  vv += res[oi];
        C[oi] = vv;
      }
    }
  }
}

__global__ void sample_m_kernel(const float* __restrict__ Q, const float* __restrict__ K,
                                const int* __restrict__ idx, float* __restrict__ Mout,
                                int Lc, int sk) {
  int gw = (blockIdx.x * blockDim.x + threadIdx.x) >> 5;
  int lane = threadIdx.x & 31;
  if (gw >= BB*NH*Lc) return;
  int l = gw % Lc, h = (gw / Lc) & 7, b = gw / (Lc * NH);
  const float* qr = Q + ((size_t)(b*Lc + l))*DM + h*HD;
  float2 q2 = *(const float2*)(qr + lane*2);
  const int* rw = idx + (size_t)l * sk;
  float mx = -3.0e38f, sm = 0.f;
  for (int u = 0; u < sk; u++) {
    const float* kr = K + ((size_t)(b*Lc + rw[u]))*DM + h*HD;
    float2 k2 = *(const float2*)(kr + lane*2);
    float p = q2.x*k2.x + q2.y*k2.y;
#pragma unroll
    for (int o = 16; o; o >>= 1) p += __shfl_xor_sync(0xffffffffu, p, o);
    mx = fmaxf(mx, p); sm += p;
  }
  if (!lane) Mout[gw] = mx - sm / (float)Lc;
}

__global__ void topk_kernel(float* __restrict__ M, int* __restrict__ top, int Lc, int ntop) {
  float* row = M + (size_t)blockIdx.x * Lc;
  __shared__ float sv[256];
  __shared__ int   si[256];
  int t = threadIdx.x;
  for (int it = 0; it < ntop; it++) {
    float bv = -3.0e38f; int bi = 0x7fffffff;
    for (int i = t; i < Lc; i += 256) {
      float vv = row[i];
      if (vv > bv) { bv = vv; bi = i; }
    }
    sv[t] = bv; si[t] = bi; __syncthreads();
    for (int s = 128; s; s >>= 1) {
      if (t < s && (sv[t+s] > sv[t] || (sv[t+s] == sv[t] && si[t+s] < si[t]))) {
        sv[t] = sv[t+s]; si[t] = si[t+s];
      }
      __syncthreads();
    }
    if (!t) { top[blockIdx.x * ntop + it] = si[0]; row[si[0]] = -3.0e38f; }
    __syncthreads();
  }
}

__global__ void vmean_kernel(const float* __restrict__ V, float* __restrict__ vm, int Lc) {
  int bh = blockIdx.x, b = bh >> 3, h = bh & 7;
  int t = threadIdx.x, d = t & 63, sl = t >> 6;
  float s = 0.f;
  for (int l = sl; l < Lc; l += 4) s += V[((size_t)(b*Lc + l))*DM + h*HD + d];
  __shared__ float sp[256];
  sp[t] = s; __syncthreads();
  if (t < 64) vm[bh*HD + t] = (sp[t] + sp[t+64] + sp[t+128] + sp[t+192]) / (float)Lc;
}

__global__ void attn_kernel(const float* __restrict__ Q, const float* __restrict__ K,
                            const float* __restrict__ V, const int* __restrict__ top,
                            float* __restrict__ upd, int Lc, int ntop) {
  int u = blockIdx.x % ntop, bh = blockIdx.x / ntop;
  int b = bh >> 3, h = bh & 7;
  int t = threadIdx.x, lane = t & 31, w = t >> 5;
  __shared__ float sc[2048];
  __shared__ float qrow[64];
  __shared__ float sr[256];
  int ql = top[bh*ntop + u];
  if (t < 64) qrow[t] = Q[((size_t)(b*Lc + ql))*DM + h*HD + t];
  __syncthreads();
  float qa = qrow[lane*2], qb = qrow[lane*2+1];
  for (int kk = w; kk < Lc; kk += 8) {
    const float* kr = K + ((size_t)(b*Lc + kk))*DM + h*HD;
    float p = qa*kr[lane*2] + qb*kr[lane*2+1];
#pragma unroll
    for (int o = 16; o; o >>= 1) p += __shfl_xor_sync(0xffffffffu, p, o);
    if (!lane) sc[kk] = p * 0.125f;
  }
  __syncthreads();
  float mx = -3.0e38f;
  for (int i = t; i < Lc; i += 256) mx = fmaxf(mx, sc[i]);
  sr[t] = mx; __syncthreads();
  for (int s = 128; s; s >>= 1) { if (t < s) sr[t] = fmaxf(sr[t], sr[t+s]); __syncthreads(); }
  mx = sr[0]; __syncthreads();
  float sum = 0.f;
  for (int i = t; i < Lc; i += 256) { float e = expf(sc[i] - mx); sc[i] = e; sum += e; }
  sr[t] = sum; __syncthreads();
  for (int s = 128; s; s >>= 1) { if (t < s) sr[t] += sr[t+s]; __syncthreads(); }
  float inv = 1.f / sr[0];
  __syncthreads();
  int d = t & 63, sl = t >> 6;
  float a = 0.f;
  for (int kk = sl; kk < Lc; kk += 4)
    a += (sc[kk] * inv) * V[((size_t)(b*Lc + kk))*DM + h*HD + d];
  sr[t] = a; __syncthreads();
  if (t < 64)
    upd[((size_t)bh*ntop + u)*HD + t] = sr[t] + sr[t+64] + sr[t+128] + sr[t+192];
}

__global__ void ctx_fill(const float* __restrict__ vm, float* __restrict__ ctx, int Lc) {
  size_t i = (size_t)blockIdx.x * blockDim.x + threadIdx.x;
  if (i >= (size_t)BB * Lc * DM) return;
  int c = (int)(i & 511);
  int b = (int)((i >> 9) / (size_t)Lc);
  ctx[i] = vm[(b*NH + (c >> 6))*HD + (c & 63)];
}

__global__ void ctx_scatter(const float* __restrict__ upd, const int* __restrict__ top,
                            float* __restrict__ ctx, int Lc, int ntop) {
  int u = blockIdx.x % ntop, bh = blockIdx.x / ntop;
  int b = bh >> 3, h = bh & 7;
  int l = top[bh*ntop + u];
  ctx[((size_t)(b*Lc + l))*DM + h*HD + threadIdx.x] =
      upd[((size_t)bh*ntop + u)*HD + threadIdx.x];
}

__global__ void ln_kernel(const float* __restrict__ X, const float* __restrict__ g,
                          const float* __restrict__ be, float* __restrict__ Y) {
  int r = blockIdx.x, t = threadIdx.x;
  const float* x = X + (size_t)r * DM;
  float* y = Y + (size_t)r * DM;
  float v0 = x[t], v1 = x[t+128], v2 = x[t+256], v3 = x[t+384];
  __shared__ float sr[128];
  sr[t] = v0+v1+v2+v3; __syncthreads();
  for (int s = 64; s; s >>= 1) { if (t < s) sr[t] += sr[t+s]; __syncthreads(); }
  float mu = sr[0] * (1.f/512.f); __syncthreads();
  float d0 = v0-mu, d1 = v1-mu, d2 = v2-mu, d3 = v3-mu;
  sr[t] = d0*d0 + d1*d1 + d2*d2 + d3*d3; __syncthreads();
  for (int s = 64; s; s >>= 1) { if (t < s) sr[t] += sr[t+s]; __syncthreads(); }
  float rstd = rsqrtf(sr[0] * (1.f/512.f) + 1e-5f);
  y[t]     = d0*rstd*g[t]     + be[t];
  y[t+128] = d1*rstd*g[t+128] + be[t+128];
  y[t+256] = d2*rstd*g[t+256] + be[t+256];
  y[t+384] = d3*rstd*g[t+384] + be[t+384];
}

__global__ void bn_stats(const float* __restrict__ Y, int M, float* __restrict__ stats) {
  int c = blockIdx.x, t = threadIdx.x;
  double s = 0.0, s2 = 0.0;
  for (int r = t; r < M; r += 256) {
    float vv = Y[(size_t)r*DM + c];
    s += vv; s2 += (double)vv*vv;
  }
  __shared__ double sh[256], sh2[256];
  sh[t] = s; sh2[t] = s2; __syncthreads();
  for (int st = 128; st; st >>= 1) {
    if (t < st) { sh[t] += sh[t+st]; sh2[t] += sh2[t+st]; }
    __syncthreads();
  }
  if (!t) {
    double mu = sh[0] / M;
    stats[c] = (float)mu;
    stats[DM + c] = (float)(sh2[0] / M - mu*mu);
  }
}

__global__ void bn_elu(float* __restrict__ Y, const float* __restrict__ stats,
                       const float* __restrict__ g, const float* __restrict__ b, int M) {
  size_t i = (size_t)blockIdx.x * blockDim.x + threadIdx.x;
  if (i >= (size_t)M * DM) return;
  int c = (int)(i & 511);
  float vv = (Y[i] - stats[c]) * rsqrtf(stats[DM+c] + 1e-5f) * g[c] + b[c];
  Y[i] = vv > 0.f ? vv : expm1f(vv);
}

__global__ void maxpool_kernel(const float* __restrict__ Y, float* __restrict__ X, int Lout) {
  size_t i = (size_t)blockIdx.x * blockDim.x + threadIdx.x;
  if (i >= (size_t)BB * Lout * DM) return;
  int c = (int)(i & 511);
  size_t bt = i >> 9;
  int b = (int)(bt / (size_t)Lout), t = (int)(bt % (size_t)Lout);
  int L = Lout * 2;
  float m = Y[((size_t)(b*L + 2*t))*DM + c];
  m = fmaxf(m, Y[((size_t)(b*L + 2*t + 1))*DM + c]);
  if (t > 0) m = fmaxf(m, Y[((size_t)(b*L + 2*t - 1))*DM + c]);
  X[i] = m;
}

extern "C" void kernel_launch(void* const* d_in, const int* in_sizes, int n_in,
                              void* d_out, int out_size) {
  const float* x_enc  = (const float*)d_in[0];
  const float* tok_w  = (const float*)d_in[1];
  const float* Wq     = (const float*)d_in[2];
  const float* bq     = (const float*)d_in[3];
  const float* Wk     = (const float*)d_in[4];
  const float* bk     = (const float*)d_in[5];
  const float* Wv     = (const float*)d_in[6];
  const float* bv     = (const float*)d_in[7];
  const float* Wo     = (const float*)d_in[8];
  const float* bo     = (const float*)d_in[9];
  const float* W1     = (const float*)d_in[10];
  const float* b1     = (const float*)d_in[11];
  const float* W2     = (const float*)d_in[12];
  const float* b2     = (const float*)d_in[13];
  const float* ln1_g  = (const float*)d_in[14];
  const float* ln1_b  = (const float*)d_in[15];
  const float* ln2_g  = (const float*)d_in[16];
  const float* ln2_b  = (const float*)d_in[17];
  const float* conv_w = (const float*)d_in[18];
  const float* conv_b = (const float*)d_in[19];
  const float* bn_g   = (const float*)d_in[20];
  const float* bn_b   = (const float*)d_in[21];
  const float* normf_g= (const float*)d_in[22];
  const float* normf_b= (const float*)d_in[23];
  const float* proj_w = (const float*)d_in[24];
  const float* proj_b = (const float*)d_in[25];
  float* out = (float*)d_out;

  float *x,*tmp,*q,*k,*v,*ctx,*ffn,*Mb,*upd,*vm,*stats;
  int *top,*idx;
  cudaGetSymbolAddress((void**)&x,   g_x);
  cudaGetSymbolAddress((void**)&tmp, g_tmp);
  cudaGetSymbolAddress((void**)&q,   g_q);
  cudaGetSymbolAddress((void**)&k,   g_k);
  cudaGetSymbolAddress((void**)&v,   g_v);
  cudaGetSymbolAddress((void**)&ctx, g_ctx);
  cudaGetSymbolAddress((void**)&ffn, g_ffn);
  cudaGetSymbolAddress((void**)&Mb,  g_M);
  cudaGetSymbolAddress((void**)&upd, g_upd);
  cudaGetSymbolAddress((void**)&vm,  g_vm);
  cudaGetSymbolAddress((void**)&stats, g_stats);
  cudaGetSymbolAddress((void**)&top, g_top);
  cudaGetSymbolAddress((void**)&idx, g_idx);

  unsigned K0s[2], K1s[2], R0s[2], R1s[2];
  tf2x32(0u, 42u, 0u, 0u, K0s[0], K1s[0]);
  tf2x32(0u, 42u, 0u, 1u, K0s[1], K1s[1]);
  tf2x32(K0s[0], K1s[0], 0u, 1u, R0s[0], R1s[0]);
  tf2x32(K0s[1], K1s[1], 0u, 1u, R0s[1], R1s[1]);

  tok_conv_pe<<<BB*2048, 512>>>(x_enc, tok_w, x);

  int Lc = 2048;
  for (int i = 0; i < 2; i++) {
    int M = BB * Lc;
    int ntop = (i == 0) ? 40 : 35;
    int sk = ntop;
    dim3 thr(256);
    dim3 g512(CDIV(512,128), CDIV(M,128));
    size_t WO = (size_t)i*512*512, BO = (size_t)i*512;

    gemm_kernel<<<g512,thr>>>(x, Wq+WO, 512,1, bq+BO, nullptr, q, M,512,512, Lc,0,0,0);
    gemm_kernel<<<g512,thr>>>(x, Wk+WO, 512,1, bk+BO, nullptr, k, M,512,512, Lc,0,0,0);
    gemm_kernel<<<g512,thr>>>(x, Wv+WO, 512,1, bv+BO, nullptr, v, M,512,512, Lc,0,0,0);

    int n = Lc * sk;
    rng_idx_kernel<<<CDIV(n,256),256>>>(R0s[i], R1s[i], Lc, n, idx);

    sample_m_kernel<<<CDIV(BB*NH*Lc*32,256),256>>>(q, k, idx, Mb, Lc, sk);
    topk_kernel<<<BB*NH,256>>>(Mb, top, Lc, ntop);
    vmean_kernel<<<BB*NH,256>>>(v, vm, Lc);
    ctx_fill<<<CDIV((size_t)M*512,256),256>>>(vm, ctx, Lc);
    attn_kernel<<<BB*NH*ntop,256>>>(q, k, v, top, upd, Lc, ntop);
    ctx_scatter<<<BB*NH*ntop,64>>>(upd, top, ctx, Lc, ntop);

    gemm_kernel<<<g512,thr>>>(ctx, Wo+WO, 512,1, bo+BO, x, tmp, M,512,512, Lc,0,0,0);
    ln_kernel<<<M,128>>>(tmp, ln1_g+BO, ln1_b+BO, x);

    dim3 gff(CDIV(DFF,128), CDIV(M,128));
    gemm_kernel<<<gff,thr>>>(x, W1+(size_t)i*DFF*512, 512,1, b1+(size_t)i*DFF, nullptr,
                             ffn, M,DFF,512, Lc,0,1,0);
    gemm_kernel<<<g512,thr>>>(ffn, W2+(size_t)i*512*DFF, DFF,1, b2+BO, x, tmp,
                              M,512,DFF, Lc,0,0,0);
    ln_kernel<<<M,128>>>(tmp, ln2_g+BO, ln2_b+BO, x);

    if (i == 0) {
      for (int kk = 0; kk < 3; kk++) {
        gemm_kernel<<<g512,thr>>>(x, conv_w + kk, 512*3, 3,
                                  kk==0 ? conv_b : nullptr, nullptr, tmp,
                                  M,512,512, Lc, kk-1, 0, kk>0 ? 1 : 0);
      }
      bn_stats<<<512,256>>>(tmp, M, stats);
      bn_elu<<<CDIV((size_t)M*512,256),256>>>(tmp, stats, bn_g, bn_b, M);
      maxpool_kernel<<<CDIV((size_t)(M/2)*512,256),256>>>(tmp, x, Lc/2);
      Lc = 1024;
    }
  }

  int M = BB * Lc;
  ln_kernel<<<M,128>>>(x, normf_g, normf_b, tmp);
  dim3 gproj(1, CDIV(M,128));
  gemm_kernel<<<gproj,dim3(256)>>>(tmp, proj_w, 512,1, proj_b, nullptr, out,
                                   M,32,512, Lc,0,0,0);
}

// round 11
// speedup vs baseline: 1.4085x; 1.1304x over previous
#include <cuda_runtime.h>
#include <math.h>
#include <stdint.h>

#define BB 4
#define DM 512
#define DFF 2048
#define NH 8
#define HD 64
#define CDIV(a,b) (((a)+(b)-1)/(b))

__device__ float g_x  [BB*2048*DM];
__device__ float g_tmp[BB*2048*DM];
__device__ float g_q  [BB*2048*DM];
__device__ float g_k  [BB*2048*DM];
__device__ float g_v  [BB*2048*DM];
__device__ float g_ctx[BB*2048*DM];
__device__ float g_ffn[BB*2048*DFF];
__device__ float g_M  [BB*NH*2048];
__device__ float g_upd[BB*NH*64*HD];
__device__ float g_vm [BB*NH*HD];
__device__ float g_stats[2*DM];
__device__ float g_wt [512*1536];
__device__ int   g_top[BB*NH*64];
__device__ int   g_idx[2048*64];

__host__ __device__ inline void tf2x32(unsigned k0, unsigned k1,
                                       unsigned x0, unsigned x1,
                                       unsigned &o0, unsigned &o1) {
  unsigned ks2 = k0 ^ k1 ^ 0x1BD11BDAu;
#define TFR(r) x0 += x1; x1 = ((x1<<(r))|(x1>>(32-(r)))); x1 ^= x0;
  x0 += k0; x1 += k1;
  TFR(13) TFR(15) TFR(26) TFR(6)
  x0 += k1;  x1 += ks2 + 1u;
  TFR(17) TFR(29) TFR(16) TFR(24)
  x0 += ks2; x1 += k0 + 2u;
  TFR(13) TFR(15) TFR(26) TFR(6)
  x0 += k0;  x1 += k1 + 3u;
  TFR(17) TFR(29) TFR(16) TFR(24)
  x0 += k1;  x1 += ks2 + 4u;
  TFR(13) TFR(15) TFR(26) TFR(6)
  x0 += ks2; x1 += k0 + 5u;
#undef TFR
  o0 = x0; o1 = x1;
}

__global__ void rng_idx_kernel(unsigned k0, unsigned k1, int Lc, int n, int* idx) {
  int j = blockIdx.x * blockDim.x + threadIdx.x;
  if (j >= n) return;
  unsigned o0, o1;
  tf2x32(k0, k1, 0u, (unsigned)j, o0, o1);
  idx[j] = (int)((o0 ^ o1) & (unsigned)(Lc - 1));
}

__global__ void tok_conv_pe(const float* __restrict__ xe, const float* __restrict__ w,
                            float* __restrict__ X) {
  __shared__ float sx[3][32];
  int bl = blockIdx.x;
  int b = bl >> 11, l = bl & 2047;
  int t = threadIdx.x;
  if (t < 96) {
    int kk = t / 32, i = t % 32;
    int l2 = (l + kk - 1 + 2048) & 2047;
    sx[kk][i] = xe[((size_t)(b*2048 + l2))*32 + i];
  }
  __syncthreads();
  const float* wr = w + (size_t)t * 96;
  float s = 0.f;
#pragma unroll
  for (int i = 0; i < 32; i++)
    s += sx[0][i]*wr[i*3] + sx[1][i]*wr[i*3+1] + sx[2][i]*wr[i*3+2];
  int j = t >> 1;
  float xf = (float)(2*j) * (float)(-(9.210340371976184/512.0));
  float divf = (float)exp((double)xf);
  float angf = (float)l * divf;
  double sv = (t & 1) ? cos((double)angf) : sin((double)angf);
  X[((size_t)bl)*DM + t] = s + (float)sv;
}

// conv_w (o, i, kk) -> wt[o][kk*512 + i]  (k-major, vectorizable)
__global__ void transpose_convw(const float* __restrict__ w, float* __restrict__ wt) {
  int i = blockIdx.x * blockDim.x + threadIdx.x;
  if (i >= 512*512*3) return;
  int kk = i % 3, ii = (i / 3) % 512, n = i / 1536;
  wt[(size_t)n*1536 + kk*512 + ii] = w[i];
}

// 128x128x16 double-buffered SGEMM, 256 thr, 8x8 microtile.
// C[M,N] = A'[M,K] @ B[N,K]^T (+bias)(+gelu)(+res).
// convmode: K=1536, A row shift = (k/512)-1 circular within Lc segments, lda=512.
__global__ void __launch_bounds__(256, 2)
gemm_kernel(const float* __restrict__ A, const float* __restrict__ B,
            int lda, int ldb,
            const float* __restrict__ bias, const float* __restrict__ res,
            float* __restrict__ C,
            int M, int N, int K, int Lc, int shift, int gelu, int convmode) {
  __shared__ float As[2][16][128];
  __shared__ float Bs[2][16][128];
  int tid = threadIdx.x;
  int bm = blockIdx.y * 128, bn = blockIdx.x * 128;
  int lrow = tid >> 1;
  int lcol = (tid & 1) * 8;

  int row = bm + lrow;
  int rr = (row < M) ? row : (M - 1);
  int b = rr / Lc, l = rr % Lc;
  const float* Ar0; const float* Ar1; const float* Ar2;
  if (convmode) {
    int lm = l - 1; if (lm < 0) lm += Lc;
    int lp = l + 1; if (lp >= Lc) lp -= Lc;
    Ar0 = A + ((size_t)(b*Lc + lm))*lda;
    Ar1 = A + ((size_t)(b*Lc + l ))*lda;
    Ar2 = A + ((size_t)(b*Lc + lp))*lda;
  } else {
    int l2 = l + shift;
    if (l2 < 0) l2 += Lc; else if (l2 >= Lc) l2 -= Lc;
    Ar0 = Ar1 = Ar2 = A + ((size_t)(b*Lc + l2))*lda;
  }
  int colB = bn + lrow;
  bool bok = (colB < N);
  const float* Brow = B + (size_t)(bok ? colB : 0) * (size_t)ldb;

  int tm = tid & 15, tn = tid >> 4;
  float acc[8][8];
#pragma unroll
  for (int i = 0; i < 8; i++)
#pragma unroll
    for (int j = 0; j < 8; j++) acc[i][j] = 0.f;

  float ra[8], rb[8];

#define PREFETCH(k0) do {                                            \
    const float* Ar = Ar1;                                           \
    int ac = (k0);                                                   \
    if (convmode) {                                                  \
      int kw = (k0) >> 9;                                            \
      Ar = (kw == 0) ? Ar0 : ((kw == 1) ? Ar1 : Ar2);                \
      ac = (k0) & 511;                                               \
    }                                                                \
    float4 a0 = *(const float4*)(Ar + ac + lcol);                    \
    float4 a1 = *(const float4*)(Ar + ac + lcol + 4);                \
    ra[0]=a0.x; ra[1]=a0.y; ra[2]=a0.z; ra[3]=a0.w;                  \
    ra[4]=a1.x; ra[5]=a1.y; ra[6]=a1.z; ra[7]=a1.w;                  \
    float4 b0 = bok ? *(const float4*)(Brow + (k0) + lcol)           \
                    : make_float4(0,0,0,0);                          \
    float4 b1 = bok ? *(const float4*)(Brow + (k0) + lcol + 4)       \
                    : make_float4(0,0,0,0);                          \
    rb[0]=b0.x; rb[1]=b0.y; rb[2]=b0.z; rb[3]=b0.w;                  \
    rb[4]=b1.x; rb[5]=b1.y; rb[6]=b1.z; rb[7]=b1.w;                  \
  } while (0)

  PREFETCH(0);
#pragma unroll
  for (int j = 0; j < 8; j++) { As[0][lcol+j][lrow] = ra[j]; Bs[0][lcol+j][lrow] = rb[j]; }
  __syncthreads();

  int nk = K >> 4;
  for (int kt = 0; kt < nk; kt++) {
    int cur = kt & 1;
    if (kt + 1 < nk) PREFETCH((kt + 1) << 4);
#pragma unroll
    for (int kk = 0; kk < 16; kk++) {
      float af[8], bf[8];
      *(float4*)(af)   = *(const float4*)&As[cur][kk][tm*4];
      *(float4*)(af+4) = *(const float4*)&As[cur][kk][64 + tm*4];
      *(float4*)(bf)   = *(const float4*)&Bs[cur][kk][tn*4];
      *(float4*)(bf+4) = *(const float4*)&Bs[cur][kk][64 + tn*4];
#pragma unroll
      for (int i = 0; i < 8; i++)
#pragma unroll
        for (int j = 0; j < 8; j++) acc[i][j] += af[i]*bf[j];
    }
    if (kt + 1 < nk) {
      int nxt = cur ^ 1;
#pragma unroll
      for (int j = 0; j < 8; j++) { As[nxt][lcol+j][lrow] = ra[j]; Bs[nxt][lcol+j][lrow] = rb[j]; }
      __syncthreads();
    }
  }
#undef PREFETCH

#pragma unroll
  for (int i = 0; i < 8; i++) {
    int r = bm + (i >> 2)*64 + tm*4 + (i & 3);
    if (r >= M) continue;
#pragma unroll
    for (int j = 0; j < 8; j++) {
      int c = bn + (j >> 2)*64 + tn*4 + (j & 3);
      if (c >= N) continue;
      float vv = acc[i][j];
      size_t oi = (size_t)r * N + c;
      if (bias) vv += bias[c];
      if (gelu) vv = 0.5f * vv * (1.f + erff(vv * 0.70710678118654752f));
      if (res)  vv += res[oi];
      C[oi] = vv;
    }
  }
}

__global__ void sample_m_kernel(const float* __restrict__ Q, const float* __restrict__ K,
                                const int* __restrict__ idx, float* __restrict__ Mout,
                                int Lc, int sk) {
  int gw = (blockIdx.x * blockDim.x + threadIdx.x) >> 5;
  int lane = threadIdx.x & 31;
  if (gw >= BB*NH*Lc) return;
  int l = gw % Lc, h = (gw / Lc) & 7, b = gw / (Lc * NH);
  const float* qr = Q + ((size_t)(b*Lc + l))*DM + h*HD;
  float2 q2 = *(const float2*)(qr + lane*2);
  const int* rw = idx + (size_t)l * sk;
  float mx = -3.0e38f, sm = 0.f;
  for (int u = 0; u < sk; u++) {
    const float* kr = K + ((size_t)(b*Lc + rw[u]))*DM + h*HD;
    float2 k2 = *(const float2*)(kr + lane*2);
    float p = q2.x*k2.x + q2.y*k2.y;
#pragma unroll
    for (int o = 16; o; o >>= 1) p += __shfl_xor_sync(0xffffffffu, p, o);
    mx = fmaxf(mx, p); sm += p;
  }
  if (!lane) Mout[gw] = mx - sm / (float)Lc;
}

__global__ void topk_kernel(float* __restrict__ M, int* __restrict__ top, int Lc, int ntop) {
  float* row = M + (size_t)blockIdx.x * Lc;
  __shared__ float sv[256];
  __shared__ int   si[256];
  int t = threadIdx.x;
  for (int it = 0; it < ntop; it++) {
    float bv = -3.0e38f; int bi = 0x7fffffff;
    for (int i = t; i < Lc; i += 256) {
      float vv = row[i];
      if (vv > bv) { bv = vv; bi = i; }
    }
    sv[t] = bv; si[t] = bi; __syncthreads();
    for (int s = 128; s; s >>= 1) {
      if (t < s && (sv[t+s] > sv[t] || (sv[t+s] == sv[t] && si[t+s] < si[t]))) {
        sv[t] = sv[t+s]; si[t] = si[t+s];
      }
      __syncthreads();
    }
    if (!t) { top[blockIdx.x * ntop + it] = si[0]; row[si[0]] = -3.0e38f; }
    __syncthreads();
  }
}

__global__ void vmean_kernel(const float* __restrict__ V, float* __restrict__ vm, int Lc) {
  int bh = blockIdx.x, b = bh >> 3, h = bh & 7;
  int t = threadIdx.x, d = t & 63, sl = t >> 6;
  float s = 0.f;
  for (int l = sl; l < Lc; l += 4) s += V[((size_t)(b*Lc + l))*DM + h*HD + d];
  __shared__ float sp[256];
  sp[t] = s; __syncthreads();
  if (t < 64) vm[bh*HD + t] = (sp[t] + sp[t+64] + sp[t+128] + sp[t+192]) / (float)Lc;
}

__global__ void attn_kernel(const float* __restrict__ Q, const float* __restrict__ K,
                            const float* __restrict__ V, const int* __restrict__ top,
                            float* __restrict__ upd, int Lc, int ntop) {
  int u = blockIdx.x % ntop, bh = blockIdx.x / ntop;
  int b = bh >> 3, h = bh & 7;
  int t = threadIdx.x, lane = t & 31, w = t >> 5;
  __shared__ float sc[2048];
  __shared__ float qrow[64];
  __shared__ float sr[256];
  int ql = top[bh*ntop + u];
  if (t < 64) qrow[t] = Q[((size_t)(b*Lc + ql))*DM + h*HD + t];
  __syncthreads();
  float qa = qrow[lane*2], qb = qrow[lane*2+1];
  for (int kk = w; kk < Lc; kk += 8) {
    const float* kr = K + ((size_t)(b*Lc + kk))*DM + h*HD;
    float p = qa*kr[lane*2] + qb*kr[lane*2+1];
#pragma unroll
    for (int o = 16; o; o >>= 1) p += __shfl_xor_sync(0xffffffffu, p, o);
    if (!lane) sc[kk] = p * 0.125f;
  }
  __syncthreads();
  float mx = -3.0e38f;
  for (int i = t; i < Lc; i += 256) mx = fmaxf(mx, sc[i]);
  sr[t] = mx; __syncthreads();
  for (int s = 128; s; s >>= 1) { if (t < s) sr[t] = fmaxf(sr[t], sr[t+s]); __syncthreads(); }
  mx = sr[0]; __syncthreads();
  float sum = 0.f;
  for (int i = t; i < Lc; i += 256) { float e = expf(sc[i] - mx); sc[i] = e; sum += e; }
  sr[t] = sum; __syncthreads();
  for (int s = 128; s; s >>= 1) { if (t < s) sr[t] += sr[t+s]; __syncthreads(); }
  float inv = 1.f / sr[0];
  __syncthreads();
  int d = t & 63, sl = t >> 6;
  float a = 0.f;
  for (int kk = sl; kk < Lc; kk += 4)
    a += (sc[kk] * inv) * V[((size_t)(b*Lc + kk))*DM + h*HD + d];
  sr[t] = a; __syncthreads();
  if (t < 64)
    upd[((size_t)bh*ntop + u)*HD + t] = sr[t] + sr[t+64] + sr[t+128] + sr[t+192];
}

__global__ void ctx_fill(const float* __restrict__ vm, float* __restrict__ ctx, int Lc) {
  size_t i = (size_t)blockIdx.x * blockDim.x + threadIdx.x;
  if (i >= (size_t)BB * Lc * DM) return;
  int c = (int)(i & 511);
  int b = (int)((i >> 9) / (size_t)Lc);
  ctx[i] = vm[(b*NH + (c >> 6))*HD + (c & 63)];
}

__global__ void ctx_scatter(const float* __restrict__ upd, const int* __restrict__ top,
                            float* __restrict__ ctx, int Lc, int ntop) {
  int u = blockIdx.x % ntop, bh = blockIdx.x / ntop;
  int b = bh >> 3, h = bh & 7;
  int l = top[bh*ntop + u];
  ctx[((size_t)(b*Lc + l))*DM + h*HD + threadIdx.x] =
      upd[((size_t)bh*ntop + u)*HD + threadIdx.x];
}

__global__ void ln_kernel(const float* __restrict__ X, const float* __restrict__ g,
                          const float* __restrict__ be, float* __restrict__ Y) {
  int r = blockIdx.x, t = threadIdx.x;
  const float* x = X + (size_t)r * DM;
  float* y = Y + (size_t)r * DM;
  float v0 = x[t], v1 = x[t+128], v2 = x[t+256], v3 = x[t+384];
  __shared__ float sr[128];
  sr[t] = v0+v1+v2+v3; __syncthreads();
  for (int s = 64; s; s >>= 1) { if (t < s) sr[t] += sr[t+s]; __syncthreads(); }
  float mu = sr[0] * (1.f/512.f); __syncthreads();
  float d0 = v0-mu, d1 = v1-mu, d2 = v2-mu, d3 = v3-mu;
  sr[t] = d0*d0 + d1*d1 + d2*d2 + d3*d3; __syncthreads();
  for (int s = 64; s; s >>= 1) { if (t < s) sr[t] += sr[t+s]; __syncthreads(); }
  float rstd = rsqrtf(sr[0] * (1.f/512.f) + 1e-5f);
  y[t]     = d0*rstd*g[t]     + be[t];
  y[t+128] = d1*rstd*g[t+128] + be[t+128];
  y[t+256] = d2*rstd*g[t+256] + be[t+256];
  y[t+384] = d3*rstd*g[t+384] + be[t+384];
}

__global__ void bn_stats(const float* __restrict__ Y, int M, float* __restrict__ stats) {
  int c = blockIdx.x, t = threadIdx.x;
  double s = 0.0, s2 = 0.0;
  for (int r = t; r < M; r += 256) {
    float vv = Y[(size_t)r*DM + c];
    s += vv; s2 += (double)vv*vv;
  }
  __shared__ double sh[256], sh2[256];
  sh[t] = s; sh2[t] = s2; __syncthreads();
  for (int st = 128; st; st >>= 1) {
    if (t < st) { sh[t] += sh[t+st]; sh2[t] += sh2[t+st]; }
    __syncthreads();
  }
  if (!t) {
    double mu = sh[0] / M;
    stats[c] = (float)mu;
    stats[DM + c] = (float)(sh2[0] / M - mu*mu);
  }
}

__global__ void bn_elu(float* __restrict__ Y, const float* __restrict__ stats,
                       const float* __restrict__ g, const float* __restrict__ b, int M) {
  size_t i = (size_t)blockIdx.x * blockDim.x + threadIdx.x;
  if (i >= (size_t)M * DM) return;
  int c = (int)(i & 511);
  float vv = (Y[i] - stats[c]) * rsqrtf(stats[DM+c] + 1e-5f) * g[c] + b[c];
  Y[i] = vv > 0.f ? vv : expm1f(vv);
}

__global__ void maxpool_kernel(const float* __restrict__ Y, float* __restrict__ X, int Lout) {
  size_t i = (size_t)blockIdx.x * blockDim.x + threadIdx.x;
  if (i >= (size_t)BB * Lout * DM) return;
  int c = (int)(i & 511);
  size_t bt = i >> 9;
  int b = (int)(bt / (size_t)Lout), t = (int)(bt % (size_t)Lout);
  int L = Lout * 2;
  float m = Y[((size_t)(b*L + 2*t))*DM + c];
  m = fmaxf(m, Y[((size_t)(b*L + 2*t + 1))*DM + c]);
  if (t > 0) m = fmaxf(m, Y[((size_t)(b*L + 2*t - 1))*DM + c]);
  X[i] = m;
}

extern "C" void kernel_launch(void* const* d_in, const int* in_sizes, int n_in,
                              void* d_out, int out_size) {
  const float* x_enc  = (const float*)d_in[0];
  const float* tok_w  = (const float*)d_in[1];
  const float* Wq     = (const float*)d_in[2];
  const float* bq     = (const float*)d_in[3];
  const float* Wk     = (const float*)d_in[4];
  const float* bk     = (const float*)d_in[5];
  const float* Wv     = (const float*)d_in[6];
  const float* bv     = (const float*)d_in[7];
  const float* Wo     = (const float*)d_in[8];
  const float* bo     = (const float*)d_in[9];
  const float* W1     = (const float*)d_in[10];
  const float* b1     = (const float*)d_in[11];
  const float* W2     = (const float*)d_in[12];
  const float* b2     = (const float*)d_in[13];
  const float* ln1_g  = (const float*)d_in[14];
  const float* ln1_b  = (const float*)d_in[15];
  const float* ln2_g  = (const float*)d_in[16];
  const float* ln2_b  = (const float*)d_in[17];
  const float* conv_w = (const float*)d_in[18];
  const float* conv_b = (const float*)d_in[19];
  const float* bn_g   = (const float*)d_in[20];
  const float* bn_b   = (const float*)d_in[21];
  const float* normf_g= (const float*)d_in[22];
  const float* normf_b= (const float*)d_in[23];
  const float* proj_w = (const float*)d_in[24];
  const float* proj_b = (const float*)d_in[25];
  float* out = (float*)d_out;

  float *x,*tmp,*q,*k,*v,*ctx,*ffn,*Mb,*upd,*vm,*stats,*wt;
  int *top,*idx;
  cudaGetSymbolAddress((void**)&x,   g_x);
  cudaGetSymbolAddress((void**)&tmp, g_tmp);
  cudaGetSymbolAddress((void**)&q,   g_q);
  cudaGetSymbolAddress((void**)&k,   g_k);
  cudaGetSymbolAddress((void**)&v,   g_v);
  cudaGetSymbolAddress((void**)&ctx, g_ctx);
  cudaGetSymbolAddress((void**)&ffn, g_ffn);
  cudaGetSymbolAddress((void**)&Mb,  g_M);
  cudaGetSymbolAddress((void**)&upd, g_upd);
  cudaGetSymbolAddress((void**)&vm,  g_vm);
  cudaGetSymbolAddress((void**)&stats, g_stats);
  cudaGetSymbolAddress((void**)&wt,  g_wt);
  cudaGetSymbolAddress((void**)&top, g_top);
  cudaGetSymbolAddress((void**)&idx, g_idx);

  unsigned K0s[2], K1s[2], R0s[2], R1s[2];
  tf2x32(0u, 42u, 0u, 0u, K0s[0], K1s[0]);
  tf2x32(0u, 42u, 0u, 1u, K0s[1], K1s[1]);
  tf2x32(K0s[0], K1s[0], 0u, 1u, R0s[0], R1s[0]);
  tf2x32(K0s[1], K1s[1], 0u, 1u, R0s[1], R1s[1]);

  tok_conv_pe<<<BB*2048, 512>>>(x_enc, tok_w, x);
  transpose_convw<<<CDIV(512*512*3,256),256>>>(conv_w, wt);

  int Lc = 2048;
  for (int i = 0; i < 2; i++) {
    int M = BB * Lc;
    int ntop = (i == 0) ? 40 : 35;
    int sk = ntop;
    dim3 thr(256);
    dim3 g512(CDIV(512,128), CDIV(M,128));
    size_t WO = (size_t)i*512*512, BO = (size_t)i*512;

    gemm_kernel<<<g512,thr>>>(x, Wq+WO, 512,512, bq+BO, nullptr, q, M,512,512, Lc,0,0,0);
    gemm_kernel<<<g512,thr>>>(x, Wk+WO, 512,512, bk+BO, nullptr, k, M,512,512, Lc,0,0,0);
    gemm_kernel<<<g512,thr>>>(x, Wv+WO, 512,512, bv+BO, nullptr, v, M,512,512, Lc,0,0,0);

    int n = Lc * sk;
    rng_idx_kernel<<<CDIV(n,256),256>>>(R0s[i], R1s[i], Lc, n, idx);

    sample_m_kernel<<<CDIV(BB*NH*Lc*32,256),256>>>(q, k, idx, Mb, Lc, sk);
    topk_kernel<<<BB*NH,256>>>(Mb, top, Lc, ntop);
    vmean_kernel<<<BB*NH,256>>>(v, vm, Lc);
    ctx_fill<<<CDIV((size_t)M*512,256),256>>>(vm, ctx, Lc);
    attn_kernel<<<BB*NH*ntop,256>>>(q, k, v, top, upd, Lc, ntop);
    ctx_scatter<<<BB*NH*ntop,64>>>(upd, top, ctx, Lc, ntop);

    gemm_kernel<<<g512,thr>>>(ctx, Wo+WO, 512,512, bo+BO, x, tmp, M,512,512, Lc,0,0,0);
    ln_kernel<<<M,128>>>(tmp, ln1_g+BO, ln1_b+BO, x);

    dim3 gff(CDIV(DFF,128), CDIV(M,128));
    gemm_kernel<<<gff,thr>>>(x, W1+(size_t)i*DFF*512, 512,512, b1+(size_t)i*DFF, nullptr,
                             ffn, M,DFF,512, Lc,0,1,0);
    gemm_kernel<<<g512,thr>>>(ffn, W2+(size_t)i*512*DFF, DFF,DFF, b2+BO, x, tmp,
                              M,512,DFF, Lc,0,0,0);
    ln_kernel<<<M,128>>>(tmp, ln2_g+BO, ln2_b+BO, x);

    if (i == 0) {
      gemm_kernel<<<g512,thr>>>(x, wt, 512,1536, conv_b, nullptr, tmp,
                                M,512,1536, Lc,0,0,1);
      bn_stats<<<512,256>>>(tmp, M, stats);
      bn_elu<<<CDIV((size_t)M*512,256),256>>>(tmp, stats, bn_g, bn_b, M);
      maxpool_kernel<<<CDIV((size_t)(M/2)*512,256),256>>>(tmp, x, Lc/2);
      Lc = 1024;
    }
  }

  int M = BB * Lc;
  ln_kernel<<<M,128>>>(x, normf_g, normf_b, tmp);
  dim3 gproj(1, CDIV(M,128));
  gemm_kernel<<<gproj,dim3(256)>>>(tmp, proj_w, 512,512, proj_b, nullptr, out,
                                   M,32,512, Lc,0,0,0);
}

// round 12
// speedup vs baseline: 1.4361x; 1.0196x over previous
#include <cuda_runtime.h>
#include <math.h>
#include <stdint.h>

#define BB 4
#define DM 512
#define DFF 2048
#define NH 8
#define HD 64
#define CDIV(a,b) (((a)+(b)-1)/(b))

__device__ float g_x  [BB*2048*DM];
__device__ float g_tmp[BB*2048*DM];
__device__ float g_q  [BB*2048*DM];
__device__ float g_k  [BB*2048*DM];
__device__ float g_v  [BB*2048*DM];
__device__ float g_ctx[BB*2048*DM];
__device__ float g_ffn[BB*2048*DFF];
__device__ float g_M  [BB*NH*2048];
__device__ float g_upd[BB*NH*64*HD];
__device__ float g_vm [BB*NH*HD];
__device__ float g_stats[2*DM];
__device__ float g_wt [512*1536];
__device__ int   g_top[BB*NH*64];
__device__ int   g_idx[2048*64];

__host__ __device__ inline void tf2x32(unsigned k0, unsigned k1,
                                       unsigned x0, unsigned x1,
                                       unsigned &o0, unsigned &o1) {
  unsigned ks2 = k0 ^ k1 ^ 0x1BD11BDAu;
#define TFR(r) x0 += x1; x1 = ((x1<<(r))|(x1>>(32-(r)))); x1 ^= x0;
  x0 += k0; x1 += k1;
  TFR(13) TFR(15) TFR(26) TFR(6)
  x0 += k1;  x1 += ks2 + 1u;
  TFR(17) TFR(29) TFR(16) TFR(24)
  x0 += ks2; x1 += k0 + 2u;
  TFR(13) TFR(15) TFR(26) TFR(6)
  x0 += k0;  x1 += k1 + 3u;
  TFR(17) TFR(29) TFR(16) TFR(24)
  x0 += k1;  x1 += ks2 + 4u;
  TFR(13) TFR(15) TFR(26) TFR(6)
  x0 += ks2; x1 += k0 + 5u;
#undef TFR
  o0 = x0; o1 = x1;
}

__global__ void rng_idx_kernel(unsigned k0, unsigned k1, int Lc, int n, int* idx) {
  int j = blockIdx.x * blockDim.x + threadIdx.x;
  if (j >= n) return;
  unsigned o0, o1;
  tf2x32(k0, k1, 0u, (unsigned)j, o0, o1);
  idx[j] = (int)((o0 ^ o1) & (unsigned)(Lc - 1));
}

__global__ void tok_conv_pe(const float* __restrict__ xe, const float* __restrict__ w,
                            float* __restrict__ X) {
  __shared__ float sx[3][32];
  int bl = blockIdx.x;
  int b = bl >> 11, l = bl & 2047;
  int t = threadIdx.x;
  if (t < 96) {
    int kk = t / 32, i = t % 32;
    int l2 = (l + kk - 1 + 2048) & 2047;
    sx[kk][i] = xe[((size_t)(b*2048 + l2))*32 + i];
  }
  __syncthreads();
  const float* wr = w + (size_t)t * 96;
  float s = 0.f;
#pragma unroll
  for (int i = 0; i < 32; i++)
    s += sx[0][i]*wr[i*3] + sx[1][i]*wr[i*3+1] + sx[2][i]*wr[i*3+2];
  int j = t >> 1;
  float xf = (float)(2*j) * (float)(-(9.210340371976184/512.0));
  float divf = (float)exp((double)xf);
  float angf = (float)l * divf;
  double sv = (t & 1) ? cos((double)angf) : sin((double)angf);
  X[((size_t)bl)*DM + t] = s + (float)sv;
}

__global__ void transpose_convw(const float* __restrict__ w, float* __restrict__ wt) {
  int i = blockIdx.x * blockDim.x + threadIdx.x;
  if (i >= 512*512*3) return;
  int kk = i % 3, ii = (i / 3) % 512, n = i / 1536;
  wt[(size_t)n*1536 + kk*512 + ii] = w[i];
}

// 128x128x16 double-buffered SGEMM, 256 thr, 8x8 microtile, packed FFMA2 inner loop.
__global__ void __launch_bounds__(256, 2)
gemm_kernel(const float* __restrict__ A, const float* __restrict__ B,
            int lda, int ldb,
            const float* __restrict__ bias, const float* __restrict__ res,
            float* __restrict__ C,
            int M, int N, int K, int Lc, int shift, int gelu, int convmode) {
  __shared__ float As[2][16][128];
  __shared__ float Bs[2][16][128];
  int tid = threadIdx.x;
  int bm = blockIdx.y * 128, bn = blockIdx.x * 128;
  int lrow = tid >> 1;
  int lcol = (tid & 1) * 8;

  int row = bm + lrow;
  int rr = (row < M) ? row : (M - 1);
  int b = rr / Lc, l = rr % Lc;
  const float* Ar0; const float* Ar1; const float* Ar2;
  if (convmode) {
    int lm = l - 1; if (lm < 0) lm += Lc;
    int lp = l + 1; if (lp >= Lc) lp -= Lc;
    Ar0 = A + ((size_t)(b*Lc + lm))*lda;
    Ar1 = A + ((size_t)(b*Lc + l ))*lda;
    Ar2 = A + ((size_t)(b*Lc + lp))*lda;
  } else {
    int l2 = l + shift;
    if (l2 < 0) l2 += Lc; else if (l2 >= Lc) l2 -= Lc;
    Ar0 = Ar1 = Ar2 = A + ((size_t)(b*Lc + l2))*lda;
  }
  int colB = bn + lrow;
  bool bok = (colB < N);
  const float* Brow = B + (size_t)(bok ? colB : 0) * (size_t)ldb;

  int tm = tid & 15, tn = tid >> 4;
  // packed accumulators: acc2[p][j] holds rows i=2p (lo), i=2p+1 (hi), col j
  unsigned long long acc2[4][8];
#pragma unroll
  for (int p = 0; p < 4; p++)
#pragma unroll
    for (int j = 0; j < 8; j++) acc2[p][j] = 0ull;

  float ra[8], rb[8];

#define PREFETCH(k0) do {                                            \
    const float* Ar = Ar1;                                           \
    int ac = (k0);                                                   \
    if (convmode) {                                                  \
      int kw = (k0) >> 9;                                            \
      Ar = (kw == 0) ? Ar0 : ((kw == 1) ? Ar1 : Ar2);                \
      ac = (k0) & 511;                                               \
    }                                                                \
    float4 a0 = *(const float4*)(Ar + ac + lcol);                    \
    float4 a1 = *(const float4*)(Ar + ac + lcol + 4);                \
    ra[0]=a0.x; ra[1]=a0.y; ra[2]=a0.z; ra[3]=a0.w;                  \
    ra[4]=a1.x; ra[5]=a1.y; ra[6]=a1.z; ra[7]=a1.w;                  \
    float4 b0 = bok ? *(const float4*)(Brow + (k0) + lcol)           \
                    : make_float4(0,0,0,0);                          \
    float4 b1 = bok ? *(const float4*)(Brow + (k0) + lcol + 4)       \
                    : make_float4(0,0,0,0);                          \
    rb[0]=b0.x; rb[1]=b0.y; rb[2]=b0.z; rb[3]=b0.w;                  \
    rb[4]=b1.x; rb[5]=b1.y; rb[6]=b1.z; rb[7]=b1.w;                  \
  } while (0)

  PREFETCH(0);
#pragma unroll
  for (int j = 0; j < 8; j++) { As[0][lcol+j][lrow] = ra[j]; Bs[0][lcol+j][lrow] = rb[j]; }
  __syncthreads();

  int nk = K >> 4;
  for (int kt = 0; kt < nk; kt++) {
    int cur = kt & 1;
    if (kt + 1 < nk) PREFETCH((kt + 1) << 4);
#pragma unroll
    for (int kk = 0; kk < 16; kk++) {
      float4 a0 = *(const float4*)&As[cur][kk][tm*4];
      float4 a1 = *(const float4*)&As[cur][kk][64 + tm*4];
      float4 b0 = *(const float4*)&Bs[cur][kk][tn*4];
      float4 b1 = *(const float4*)&Bs[cur][kk][64 + tn*4];
      unsigned long long ap[4];
      asm("mov.b64 %0,{%1,%2};" : "=l"(ap[0]) : "f"(a0.x), "f"(a0.y));
      asm("mov.b64 %0,{%1,%2};" : "=l"(ap[1]) : "f"(a0.z), "f"(a0.w));
      asm("mov.b64 %0,{%1,%2};" : "=l"(ap[2]) : "f"(a1.x), "f"(a1.y));
      asm("mov.b64 %0,{%1,%2};" : "=l"(ap[3]) : "f"(a1.z), "f"(a1.w));
      float bf[8] = {b0.x,b0.y,b0.z,b0.w,b1.x,b1.y,b1.z,b1.w};
#pragma unroll
      for (int j = 0; j < 8; j++) {
        unsigned long long bb;
        asm("mov.b64 %0,{%1,%1};" : "=l"(bb) : "f"(bf[j]));
#pragma unroll
        for (int p = 0; p < 4; p++)
          asm("fma.rn.f32x2 %0,%1,%2,%0;" : "+l"(acc2[p][j]) : "l"(ap[p]), "l"(bb));
      }
    }
    if (kt + 1 < nk) {
      int nxt = cur ^ 1;
#pragma unroll
      for (int j = 0; j < 8; j++) { As[nxt][lcol+j][lrow] = ra[j]; Bs[nxt][lcol+j][lrow] = rb[j]; }
      __syncthreads();
    }
  }
#undef PREFETCH

#pragma unroll
  for (int p = 0; p < 4; p++) {
#pragma unroll
    for (int h = 0; h < 2; h++) {
      int i = 2*p + h;
      int r = bm + (i >> 2)*64 + tm*4 + (i & 3);
      if (r >= M) continue;
#pragma unroll
      for (int j = 0; j < 8; j++) {
        float lo, hi;
        asm("mov.b64 {%0,%1},%2;" : "=f"(lo), "=f"(hi) : "l"(acc2[p][j]));
        float vv = h ? hi : lo;
        int c = bn + (j >> 2)*64 + tn*4 + (j & 3);
        if (c >= N) continue;
        size_t oi = (size_t)r * N + c;
        if (bias) vv += bias[c];
        if (gelu) vv = 0.5f * vv * (1.f + erff(vv * 0.70710678118654752f));
        if (res)  vv += res[oi];
        C[oi] = vv;
      }
    }
  }
}

__global__ void sample_m_kernel(const float* __restrict__ Q, const float* __restrict__ K,
                                const int* __restrict__ idx, float* __restrict__ Mout,
                                int Lc, int sk) {
  int gw = (blockIdx.x * blockDim.x + threadIdx.x) >> 5;
  int lane = threadIdx.x & 31;
  if (gw >= BB*NH*Lc) return;
  int l = gw % Lc, h = (gw / Lc) & 7, b = gw / (Lc * NH);
  const float* qr = Q + ((size_t)(b*Lc + l))*DM + h*HD;
  float2 q2 = *(const float2*)(qr + lane*2);
  const int* rw = idx + (size_t)l * sk;
  float mx = -3.0e38f, sm = 0.f;
  for (int u = 0; u < sk; u++) {
    const float* kr = K + ((size_t)(b*Lc + rw[u]))*DM + h*HD;
    float2 k2 = *(const float2*)(kr + lane*2);
    float p = q2.x*k2.x + q2.y*k2.y;
#pragma unroll
    for (int o = 16; o; o >>= 1) p += __shfl_xor_sync(0xffffffffu, p, o);
    mx = fmaxf(mx, p); sm += p;
  }
  if (!lane) Mout[gw] = mx - sm / (float)Lc;
}

__global__ void topk_kernel(float* __restrict__ M, int* __restrict__ top, int Lc, int ntop) {
  float* row = M + (size_t)blockIdx.x * Lc;
  __shared__ float sv[256];
  __shared__ int   si[256];
  int t = threadIdx.x;
  for (int it = 0; it < ntop; it++) {
    float bv = -3.0e38f; int bi = 0x7fffffff;
    for (int i = t; i < Lc; i += 256) {
      float vv = row[i];
      if (vv > bv) { bv = vv; bi = i; }
    }
    sv[t] = bv; si[t] = bi; __syncthreads();
    for (int s = 128; s; s >>= 1) {
      if (t < s && (sv[t+s] > sv[t] || (sv[t+s] == sv[t] && si[t+s] < si[t]))) {
        sv[t] = sv[t+s]; si[t] = si[t+s];
      }
      __syncthreads();
    }
    if (!t) { top[blockIdx.x * ntop + it] = si[0]; row[si[0]] = -3.0e38f; }
    __syncthreads();
  }
}

__global__ void vmean_kernel(const float* __restrict__ V, float* __restrict__ vm, int Lc) {
  int bh = blockIdx.x, b = bh >> 3, h = bh & 7;
  int t = threadIdx.x, d = t & 63, sl = t >> 6;
  float s = 0.f;
  for (int l = sl; l < Lc; l += 4) s += V[((size_t)(b*Lc + l))*DM + h*HD + d];
  __shared__ float sp[256];
  sp[t] = s; __syncthreads();
  if (t < 64) vm[bh*HD + t] = (sp[t] + sp[t+64] + sp[t+128] + sp[t+192]) / (float)Lc;
}

__global__ void attn_kernel(const float* __restrict__ Q, const float* __restrict__ K,
                            const float* __restrict__ V, const int* __restrict__ top,
                            float* __restrict__ upd, int Lc, int ntop) {
  int u = blockIdx.x % ntop, bh = blockIdx.x / ntop;
  int b = bh >> 3, h = bh & 7;
  int t = threadIdx.x, lane = t & 31, w = t >> 5;
  __shared__ float sc[2048];
  __shared__ float qrow[64];
  __shared__ float sr[256];
  int ql = top[bh*ntop + u];
  if (t < 64) qrow[t] = Q[((size_t)(b*Lc + ql))*DM + h*HD + t];
  __syncthreads();
  float qa = qrow[lane*2], qb = qrow[lane*2+1];
  for (int kk = w; kk < Lc; kk += 8) {
    const float* kr = K + ((size_t)(b*Lc + kk))*DM + h*HD;
    float p = qa*kr[lane*2] + qb*kr[lane*2+1];
#pragma unroll
    for (int o = 16; o; o >>= 1) p += __shfl_xor_sync(0xffffffffu, p, o);
    if (!lane) sc[kk] = p * 0.125f;
  }
  __syncthreads();
  float mx = -3.0e38f;
  for (int i = t; i < Lc; i += 256) mx = fmaxf(mx, sc[i]);
  sr[t] = mx; __syncthreads();
  for (int s = 128; s; s >>= 1) { if (t < s) sr[t] = fmaxf(sr[t], sr[t+s]); __syncthreads(); }
  mx = sr[0]; __syncthreads();
  float sum = 0.f;
  for (int i = t; i < Lc; i += 256) { float e = expf(sc[i] - mx); sc[i] = e; sum += e; }
  sr[t] = sum; __syncthreads();
  for (int s = 128; s; s >>= 1) { if (t < s) sr[t] += sr[t+s]; __syncthreads(); }
  float inv = 1.f / sr[0];
  __syncthreads();
  int d = t & 63, sl = t >> 6;
  float a = 0.f;
  for (int kk = sl; kk < Lc; kk += 4)
    a += (sc[kk] * inv) * V[((size_t)(b*Lc + kk))*DM + h*HD + d];
  sr[t] = a; __syncthreads();
  if (t < 64)
    upd[((size_t)bh*ntop + u)*HD + t] = sr[t] + sr[t+64] + sr[t+128] + sr[t+192];
}

__global__ void ctx_fill(const float* __restrict__ vm, float* __restrict__ ctx, int Lc) {
  size_t i = (size_t)blockIdx.x * blockDim.x + threadIdx.x;
  if (i >= (size_t)BB * Lc * DM) return;
  int c = (int)(i & 511);
  int b = (int)((i >> 9) / (size_t)Lc);
  ctx[i] = vm[(b*NH + (c >> 6))*HD + (c & 63)];
}

__global__ void ctx_scatter(const float* __restrict__ upd, const int* __restrict__ top,
                            float* __restrict__ ctx, int Lc, int ntop) {
  int u = blockIdx.x % ntop, bh = blockIdx.x / ntop;
  int b = bh >> 3, h = bh & 7;
  int l = top[bh*ntop + u];
  ctx[((size_t)(b*Lc + l))*DM + h*HD + threadIdx.x] =
      upd[((size_t)bh*ntop + u)*HD + threadIdx.x];
}

__global__ void ln_kernel(const float* __restrict__ X, const float* __restrict__ g,
                          const float* __restrict__ be, float* __restrict__ Y) {
  int r = blockIdx.x, t = threadIdx.x;
  const float* x = X + (size_t)r * DM;
  float* y = Y + (size_t)r * DM;
  float v0 = x[t], v1 = x[t+128], v2 = x[t+256], v3 = x[t+384];
  __shared__ float sr[128];
  sr[t] = v0+v1+v2+v3; __syncthreads();
  for (int s = 64; s; s >>= 1) { if (t < s) sr[t] += sr[t+s]; __syncthreads(); }
  float mu = sr[0] * (1.f/512.f); __syncthreads();
  float d0 = v0-mu, d1 = v1-mu, d2 = v2-mu, d3 = v3-mu;
  sr[t] = d0*d0 + d1*d1 + d2*d2 + d3*d3; __syncthreads();
  for (int s = 64; s; s >>= 1) { if (t < s) sr[t] += sr[t+s]; __syncthreads(); }
  float rstd = rsqrtf(sr[0] * (1.f/512.f) + 1e-5f);
  y[t]     = d0*rstd*g[t]     + be[t];
  y[t+128] = d1*rstd*g[t+128] + be[t+128];
  y[t+256] = d2*rstd*g[t+256] + be[t+256];
  y[t+384] = d3*rstd*g[t+384] + be[t+384];
}

__global__ void bn_stats(const float* __restrict__ Y, int M, float* __restrict__ stats) {
  int c = blockIdx.x, t = threadIdx.x;
  double s = 0.0, s2 = 0.0;
  for (int r = t; r < M; r += 256) {
    float vv = Y[(size_t)r*DM + c];
    s += vv; s2 += (double)vv*vv;
  }
  __shared__ double sh[256], sh2[256];
  sh[t] = s; sh2[t] = s2; __syncthreads();
  for (int st = 128; st; st >>= 1) {
    if (t < st) { sh[t] += sh[t+st]; sh2[t] += sh2[t+st]; }
    __syncthreads();
  }
  if (!t) {
    double mu = sh[0] / M;
    stats[c] = (float)mu;
    stats[DM + c] = (float)(sh2[0] / M - mu*mu);
  }
}

__global__ void bn_elu(float* __restrict__ Y, const float* __restrict__ stats,
                       const float* __restrict__ g, const float* __restrict__ b, int M) {
  size_t i = (size_t)blockIdx.x * blockDim.x + threadIdx.x;
  if (i >= (size_t)M * DM) return;
  int c = (int)(i & 511);
  float vv = (Y[i] - stats[c]) * rsqrtf(stats[DM+c] + 1e-5f) * g[c] + b[c];
  Y[i] = vv > 0.f ? vv : expm1f(vv);
}

__global__ void maxpool_kernel(const float* __restrict__ Y, float* __restrict__ X, int Lout) {
  size_t i = (size_t)blockIdx.x * blockDim.x + threadIdx.x;
  if (i >= (size_t)BB * Lout * DM) return;
  int c = (int)(i & 511);
  size_t bt = i >> 9;
  int b = (int)(bt / (size_t)Lout), t = (int)(bt % (size_t)Lout);
  int L = Lout * 2;
  float m = Y[((size_t)(b*L + 2*t))*DM + c];
  m = fmaxf(m, Y[((size_t)(b*L + 2*t + 1))*DM + c]);
  if (t > 0) m = fmaxf(m, Y[((size_t)(b*L + 2*t - 1))*DM + c]);
  X[i] = m;
}

extern "C" void kernel_launch(void* const* d_in, const int* in_sizes, int n_in,
                              void* d_out, int out_size) {
  const float* x_enc  = (const float*)d_in[0];
  const float* tok_w  = (const float*)d_in[1];
  const float* Wq     = (const float*)d_in[2];
  const float* bq     = (const float*)d_in[3];
  const float* Wk     = (const float*)d_in[4];
  const float* bk     = (const float*)d_in[5];
  const float* Wv     = (const float*)d_in[6];
  const float* bv     = (const float*)d_in[7];
  const float* Wo     = (const float*)d_in[8];
  const float* bo     = (const float*)d_in[9];
  const float* W1     = (const float*)d_in[10];
  const float* b1     = (const float*)d_in[11];
  const float* W2     = (const float*)d_in[12];
  const float* b2     = (const float*)d_in[13];
  const float* ln1_g  = (const float*)d_in[14];
  const float* ln1_b  = (const float*)d_in[15];
  const float* ln2_g  = (const float*)d_in[16];
  const float* ln2_b  = (const float*)d_in[17];
  const float* conv_w = (const float*)d_in[18];
  const float* conv_b = (const float*)d_in[19];
  const float* bn_g   = (const float*)d_in[20];
  const float* bn_b   = (const float*)d_in[21];
  const float* normf_g= (const float*)d_in[22];
  const float* normf_b= (const float*)d_in[23];
  const float* proj_w = (const float*)d_in[24];
  const float* proj_b = (const float*)d_in[25];
  float* out = (float*)d_out;

  float *x,*tmp,*q,*k,*v,*ctx,*ffn,*Mb,*upd,*vm,*stats,*wt;
  int *top,*idx;
  cudaGetSymbolAddress((void**)&x,   g_x);
  cudaGetSymbolAddress((void**)&tmp, g_tmp);
  cudaGetSymbolAddress((void**)&q,   g_q);
  cudaGetSymbolAddress((void**)&k,   g_k);
  cudaGetSymbolAddress((void**)&v,   g_v);
  cudaGetSymbolAddress((void**)&ctx, g_ctx);
  cudaGetSymbolAddress((void**)&ffn, g_ffn);
  cudaGetSymbolAddress((void**)&Mb,  g_M);
  cudaGetSymbolAddress((void**)&upd, g_upd);
  cudaGetSymbolAddress((void**)&vm,  g_vm);
  cudaGetSymbolAddress((void**)&stats, g_stats);
  cudaGetSymbolAddress((void**)&wt,  g_wt);
  cudaGetSymbolAddress((void**)&top, g_top);
  cudaGetSymbolAddress((void**)&idx, g_idx);

  unsigned K0s[2], K1s[2], R0s[2], R1s[2];
  tf2x32(0u, 42u, 0u, 0u, K0s[0], K1s[0]);
  tf2x32(0u, 42u, 0u, 1u, K0s[1], K1s[1]);
  tf2x32(K0s[0], K1s[0], 0u, 1u, R0s[0], R1s[0]);
  tf2x32(K0s[1], K1s[1], 0u, 1u, R0s[1], R1s[1]);

  tok_conv_pe<<<BB*2048, 512>>>(x_enc, tok_w, x);
  transpose_convw<<<CDIV(512*512*3,256),256>>>(conv_w, wt);

  int Lc = 2048;
  for (int i = 0; i < 2; i++) {
    int M = BB * Lc;
    int ntop = (i == 0) ? 40 : 35;
    int sk = ntop;
    dim3 thr(256);
    dim3 g512(CDIV(512,128), CDIV(M,128));
    size_t WO = (size_t)i*512*512, BO = (size_t)i*512;

    gemm_kernel<<<g512,thr>>>(x, Wq+WO, 512,512, bq+BO, nullptr, q, M,512,512, Lc,0,0,0);
    gemm_kernel<<<g512,thr>>>(x, Wk+WO, 512,512, bk+BO, nullptr, k, M,512,512, Lc,0,0,0);
    gemm_kernel<<<g512,thr>>>(x, Wv+WO, 512,512, bv+BO, nullptr, v, M,512,512, Lc,0,0,0);

    int n = Lc * sk;
    rng_idx_kernel<<<CDIV(n,256),256>>>(R0s[i], R1s[i], Lc, n, idx);

    sample_m_kernel<<<CDIV(BB*NH*Lc*32,256),256>>>(q, k, idx, Mb, Lc, sk);
    topk_kernel<<<BB*NH,256>>>(Mb, top, Lc, ntop);
    vmean_kernel<<<BB*NH,256>>>(v, vm, Lc);
    ctx_fill<<<CDIV((size_t)M*512,256),256>>>(vm, ctx, Lc);
    attn_kernel<<<BB*NH*ntop,256>>>(q, k, v, top, upd, Lc, ntop);
    ctx_scatter<<<BB*NH*ntop,64>>>(upd, top, ctx, Lc, ntop);

    gemm_kernel<<<g512,thr>>>(ctx, Wo+WO, 512,512, bo+BO, x, tmp, M,512,512, Lc,0,0,0);
    ln_kernel<<<M,128>>>(tmp, ln1_g+BO, ln1_b+BO, x);

    dim3 gff(CDIV(DFF,128), CDIV(M,128));
    gemm_kernel<<<gff,thr>>>(x, W1+(size_t)i*DFF*512, 512,512, b1+(size_t)i*DFF, nullptr,
                             ffn, M,DFF,512, Lc,0,1,0);
    gemm_kernel<<<g512,thr>>>(ffn, W2+(size_t)i*512*DFF, DFF,DFF, b2+BO, x, tmp,
                              M,512,DFF, Lc,0,0,0);
    ln_kernel<<<M,128>>>(tmp, ln2_g+BO, ln2_b+BO, x);

    if (i == 0) {
      gemm_kernel<<<g512,thr>>>(x, wt, 512,1536, conv_b, nullptr, tmp,
                                M,512,1536, Lc,0,0,1);
      bn_stats<<<512,256>>>(tmp, M, stats);
      bn_elu<<<CDIV((size_t)M*512,256),256>>>(tmp, stats, bn_g, bn_b, M);
      maxpool_kernel<<<CDIV((size_t)(M/2)*512,256),256>>>(tmp, x, Lc/2);
      Lc = 1024;
    }
  }

  int M = BB * Lc;
  ln_kernel<<<M,128>>>(x, normf_g, normf_b, tmp);
  dim3 gproj(1, CDIV(M,128));
  gemm_kernel<<<gproj,dim3(256)>>>(tmp, proj_w, 512,512, proj_b, nullptr, out,
                                   M,32,512, Lc,0,0,0);
}